// round 10
// baseline (speedup 1.0000x reference)
#include <cuda_runtime.h>
#include <cstdint>

#define LD 260
#define XMF 0
#define HF  (64*LD)
#define WBF (128*LD)
#define PAR (192*LD)
#define P_F1B (PAR)
#define P_F2B (PAR+64)
#define P_F3B (PAR+128)
#define P_B1  (PAR+160)
#define P_B2  (PAR+416)
#define P_W3  (PAR+672)
#define P_B3  (PAR+928)
#define SMEMB ((PAR+932)*4)

__device__ __forceinline__ float rt(float x){
    uint32_t u; asm("cvt.rna.tf32.f32 %0, %1;" : "=r"(u) : "f"(x));
    return __uint_as_float(u);
}
__device__ __forceinline__ void mma8(float* d, uint32_t a0,uint32_t a1,uint32_t a2,uint32_t a3,
                                     uint32_t b0,uint32_t b1){
    asm("mma.sync.aligned.m16n8k8.row.col.f32.tf32.tf32.f32 "
        "{%0,%1,%2,%3},{%4,%5,%6,%7},{%8,%9},{%0,%1,%2,%3};"
        : "+f"(d[0]),"+f"(d[1]),"+f"(d[2]),"+f"(d[3])
        : "r"(a0),"r"(a1),"r"(a2),"r"(a3),"r"(b0),"r"(b1));
}
// warp tile m16 x (NS*8), K = KS*8. A row-major [16+ x K] at stride LD. W = [N][K] rows at stride LD.
template<int KS,int NS>
__device__ __forceinline__ void mt(float (&acc)[4][4], const float* A, const float* W){
    const int lane = threadIdx.x & 31, g = lane >> 2, l4 = lane & 3;
    const uint32_t* a = (const uint32_t*)(A + g*LD + l4);
    const uint32_t* w = (const uint32_t*)(W + g*LD + l4);
    #pragma unroll 8
    for (int k = 0; k < KS; k++) {
        uint32_t a0 = a[0], a1 = a[8*LD], a2 = a[4], a3 = a[8*LD+4];
        #pragma unroll
        for (int n = 0; n < NS; n++)
            mma8(acc[n], a0,a1,a2,a3, w[n*8*LD], w[n*8*LD+4]);
        a += 8; w += 8;
    }
}
__device__ __forceinline__ void ldchunk(float* sm, const float* W){  // [64 x 256] -> WB, tf32-rounded
    const float4* s4 = (const float4*)W;
    #pragma unroll 4
    for (int i = 0; i < 16; i++) {
        int q = threadIdx.x + i*256, row = q >> 6, c4 = q & 63;
        float4 v = s4[q];
        v.x=rt(v.x); v.y=rt(v.y); v.z=rt(v.z); v.w=rt(v.w);
        *(float4*)&sm[WBF + row*LD + c4*4] = v;
    }
}

__global__ void __launch_bounds__(256, 1)
actor_kernel(const float* __restrict__ x,  const float* __restrict__ m,
             const float* __restrict__ f1w, const float* __restrict__ f1b,
             const float* __restrict__ f2w, const float* __restrict__ f2b,
             const float* __restrict__ f3w, const float* __restrict__ f3b,
             const float* __restrict__ w1,  const float* __restrict__ b1,
             const float* __restrict__ w2,  const float* __restrict__ b2,
             const float* __restrict__ w3,  const float* __restrict__ b3,
             float* __restrict__ out, int Bn)
{
    extern __shared__ float sm[];
    const int tid = threadIdx.x, wid = tid >> 5, lane = tid & 31;
    const int g = lane >> 2, l4 = lane & 3;
    const int nh = wid & 1, rbase = (wid >> 1) * 16;
    const long r0 = (long)blockIdx.x * 64;

    // params
    if (tid < 64) { sm[P_F1B+tid] = f1b[tid]; sm[P_F2B+tid] = f2b[tid]; }
    if (tid < 32) sm[P_F3B+tid] = f3b[tid];
    sm[P_B1+tid] = b1[tid]; sm[P_B2+tid] = b2[tid]; sm[P_W3+tid] = w3[tid];
    if (tid == 0) sm[P_B3] = b3[0];
    // x (tf32 raw) -> XM cols 0-127 ; tanh(m) -> XM cols 128-255
    {
        const float4* x4 = (const float4*)(x + r0*128);
        const float4* m4 = (const float4*)(m + r0*128);
        #pragma unroll 4
        for (int i = 0; i < 8; i++) {
            int q = tid + i*256, row = q >> 5, c4 = q & 31;
            float4 v = x4[q];
            v.x=rt(v.x); v.y=rt(v.y); v.z=rt(v.z); v.w=rt(v.w);
            *(float4*)&sm[XMF + row*LD + c4*4] = v;
            float4 u = m4[q];
            u.x=rt(tanhf(u.x)); u.y=rt(tanhf(u.y)); u.z=rt(tanhf(u.z)); u.w=rt(tanhf(u.w));
            *(float4*)&sm[XMF + row*LD + 128 + c4*4] = u;
        }
        const float4* s4 = (const float4*)f1w;   // [64x128]
        #pragma unroll 4
        for (int i = 0; i < 8; i++) {
            int q = tid + i*256, row = q >> 5, c4 = q & 31;
            float4 v = s4[q];
            v.x=rt(v.x); v.y=rt(v.y); v.z=rt(v.z); v.w=rt(v.w);
            *(float4*)&sm[WBF + row*LD + c4*4] = v;
        }
    }
    __syncthreads();

    // ---- fc1: [64x64] = x @ f1w^T ; store raw+bias to H cols 0-63 ----
    {
        int nb = nh * 32;
        float ac[4][4] = {};
        mt<16,4>(ac, sm + XMF + rbase*LD, sm + WBF + nb*LD);
        #pragma unroll
        for (int n = 0; n < 4; n++) {
            int cb = nb + n*8 + l4*2, r = rbase + g;
            sm[HF + r*LD + cb]       = ac[n][0] + sm[P_F1B+cb];
            sm[HF + r*LD + cb+1]     = ac[n][1] + sm[P_F1B+cb+1];
            sm[HF + (r+8)*LD + cb]   = ac[n][2] + sm[P_F1B+cb];
            sm[HF + (r+8)*LD + cb+1] = ac[n][3] + sm[P_F1B+cb+1];
        }
    }
    __syncthreads();
    // ---- fc1 epi (l2norm+tanh) || tanh(x) in place ; then f2w -> WB ----
    if (tid < 64) {
        float v[64], ss = 0.f;
        #pragma unroll
        for (int j = 0; j < 64; j++) { v[j] = sm[HF + tid*LD + j]; ss += v[j]*v[j]; }
        float inv = 1.0f / fmaxf(sqrtf(ss), 1e-12f);
        #pragma unroll
        for (int j = 0; j < 64; j++) sm[HF + tid*LD + j] = rt(tanhf(v[j]*inv));
    } else {
        for (int i = tid - 64; i < 2048; i += 192) {
            int row = i >> 5, c4 = i & 31;
            float4* p = (float4*)&sm[XMF + row*LD + c4*4];
            float4 v = *p;
            v.x=rt(tanhf(v.x)); v.y=rt(tanhf(v.y)); v.z=rt(tanhf(v.z)); v.w=rt(tanhf(v.w));
            *p = v;
        }
    }
    {
        const float4* s4 = (const float4*)f2w;   // [64x192]
        #pragma unroll 4
        for (int i = 0; i < 12; i++) {
            int q = tid + i*256, row = q / 48, c4 = q - row*48;
            float4 v = s4[q];
            v.x=rt(v.x); v.y=rt(v.y); v.z=rt(v.z); v.w=rt(v.w);
            *(float4*)&sm[WBF + row*LD + c4*4] = v;
        }
    }
    __syncthreads();

    // ---- fc2: K=192 = [z(H 0-63) | tanh(m)(XM 128-255)] -> tanh -> H cols 64-127 ----
    {
        int nb = nh * 32;
        float ac[4][4] = {};
        mt<8,4>(ac, sm + HF + rbase*LD, sm + WBF + nb*LD);
        mt<16,4>(ac, sm + XMF + rbase*LD + 128, sm + WBF + nb*LD + 64);
        #pragma unroll
        for (int n = 0; n < 4; n++) {
            int cb = nb + n*8 + l4*2, r = rbase + g;
            sm[HF + r*LD + 64+cb]       = rt(tanhf(ac[n][0] + sm[P_F2B+cb]));
            sm[HF + r*LD + 64+cb+1]     = rt(tanhf(ac[n][1] + sm[P_F2B+cb+1]));
            sm[HF + (r+8)*LD + 64+cb]   = rt(tanhf(ac[n][2] + sm[P_F2B+cb]));
            sm[HF + (r+8)*LD + 64+cb+1] = rt(tanhf(ac[n][3] + sm[P_F2B+cb+1]));
        }
    }
    __syncthreads();
    {   // f3w [32x64] -> WB
        const float4* s4 = (const float4*)f3w;
        for (int q = tid; q < 512; q += 256) {
            int row = q >> 4, c4 = q & 15;
            float4 v = s4[q];
            v.x=rt(v.x); v.y=rt(v.y); v.z=rt(v.z); v.w=rt(v.w);
            *(float4*)&sm[WBF + row*LD + c4*4] = v;
        }
    }
    __syncthreads();
    // ---- fc3: [64x32], K=64 (H cols 64-127) -> raw+bias -> H cols 0-31 ----
    {
        int nb = nh * 16;
        float ac[4][4] = {};
        mt<8,2>(ac, sm + HF + rbase*LD + 64, sm + WBF + nb*LD);
        #pragma unroll
        for (int n = 0; n < 2; n++) {
            int cb = nb + n*8 + l4*2, r = rbase + g;
            sm[HF + r*LD + cb]       = ac[n][0] + sm[P_F3B+cb];
            sm[HF + r*LD + cb+1]     = ac[n][1] + sm[P_F3B+cb+1];
            sm[HF + (r+8)*LD + cb]   = ac[n][2] + sm[P_F3B+cb];
            sm[HF + (r+8)*LD + cb+1] = ac[n][3] + sm[P_F3B+cb+1];
        }
    }
    __syncthreads();
    // ---- fc3 epi: l2norm -> msg out ; then w1 chunk0 -> WB ----
    if (tid < 64) {
        float v[32], ss = 0.f;
        #pragma unroll
        for (int j = 0; j < 32; j++) { v[j] = sm[HF + tid*LD + j]; ss += v[j]*v[j]; }
        float inv = 1.0f / fmaxf(sqrtf(ss), 1e-12f);
        float4* og = (float4*)(out + (r0 + tid)*32);
        #pragma unroll
        for (int j = 0; j < 32; j += 4)
            og[j>>2] = make_float4(v[j]*inv, v[j+1]*inv, v[j+2]*inv, v[j+3]*inv);
    }
    ldchunk(sm, w1);
    __syncthreads();

    // ---- action L1: h1 = relu(xm @ w1^T + b1) -> H (4 chunks of 64) ----
    for (int ch = 0; ch < 4; ch++) {
        int nb = nh * 32;
        float ac[4][4] = {};
        mt<32,4>(ac, sm + XMF + rbase*LD, sm + WBF + nb*LD);
        #pragma unroll
        for (int n = 0; n < 4; n++) {
            int gc = ch*64 + nb + n*8 + l4*2, r = rbase + g;
            sm[HF + r*LD + gc]       = rt(fmaxf(ac[n][0] + sm[P_B1+gc],   0.f));
            sm[HF + r*LD + gc+1]     = rt(fmaxf(ac[n][1] + sm[P_B1+gc+1], 0.f));
            sm[HF + (r+8)*LD + gc]   = rt(fmaxf(ac[n][2] + sm[P_B1+gc],   0.f));
            sm[HF + (r+8)*LD + gc+1] = rt(fmaxf(ac[n][3] + sm[P_B1+gc+1], 0.f));
        }
        __syncthreads();
        ldchunk(sm, (ch < 3) ? w1 + (ch+1)*64*256 : w2);
        __syncthreads();
    }
    // ---- action L2: h2 = relu(h1 @ w2^T + b2) -> XM (raw fp32) ----
    for (int ch = 0; ch < 4; ch++) {
        int nb = nh * 32;
        float ac[4][4] = {};
        mt<32,4>(ac, sm + HF + rbase*LD, sm + WBF + nb*LD);
        #pragma unroll
        for (int n = 0; n < 4; n++) {
            int gc = ch*64 + nb + n*8 + l4*2, r = rbase + g;
            sm[XMF + r*LD + gc]       = fmaxf(ac[n][0] + sm[P_B2+gc],   0.f);
            sm[XMF + r*LD + gc+1]     = fmaxf(ac[n][1] + sm[P_B2+gc+1], 0.f);
            sm[XMF + (r+8)*LD + gc]   = fmaxf(ac[n][2] + sm[P_B2+gc],   0.f);
            sm[XMF + (r+8)*LD + gc+1] = fmaxf(ac[n][3] + sm[P_B2+gc+1], 0.f);
        }
        __syncthreads();
        if (ch < 3) { ldchunk(sm, w2 + (ch+1)*64*256); __syncthreads(); }
    }
    // ---- final: action = tanh(h2 . w3 + b3) ----
    if (tid < 64) {
        float s = sm[P_B3];
        #pragma unroll 8
        for (int j = 0; j < 64; j++) {
            float4 h = *(float4*)&sm[XMF + tid*LD + j*4];
            float4 w = *(float4*)&sm[P_W3 + j*4];
            s += h.x*w.x + h.y*w.y + h.z*w.z + h.w*w.w;
        }
        out[(long)Bn*32 + r0 + tid] = tanhf(s);
    }
}

extern "C" void kernel_launch(void* const* d_in, const int* in_sizes, int n_in,
                              void* d_out, int out_size) {
    const float* x   = (const float*)d_in[0];
    const float* m   = (const float*)d_in[1];
    const float* f1w = (const float*)d_in[2];
    const float* f1b = (const float*)d_in[3];
    const float* f2w = (const float*)d_in[4];
    const float* f2b = (const float*)d_in[5];
    const float* f3w = (const float*)d_in[6];
    const float* f3b = (const float*)d_in[7];
    const float* w1  = (const float*)d_in[8];
    const float* b1  = (const float*)d_in[9];
    const float* w2  = (const float*)d_in[10];
    const float* b2  = (const float*)d_in[11];
    const float* w3  = (const float*)d_in[12];
    const float* b3  = (const float*)d_in[13];
    float* out = (float*)d_out;

    int Bn = in_sizes[0] / 128;
    cudaFuncSetAttribute(actor_kernel, cudaFuncAttributeMaxDynamicSharedMemorySize, SMEMB);
    actor_kernel<<<Bn / 64, 256, SMEMB>>>(x, m, f1w, f1b, f2w, f2b, f3w, f3b,
                                          w1, b1, w2, b2, w3, b3, out, Bn);
}

// round 11
// speedup vs baseline: 1.4114x; 1.4114x over previous
#include <cuda_runtime.h>
#include <cstdint>

// ---------------- smem float offsets ----------------
#define XMF 0           // activation plane 64x260 (x|tanh(m), later h1)
#define WB0F 16640      // weight ping buffer 64x260
#define WB1F 33280      // weight pong buffer 64x260
// msg-branch overlays inside the WB region (dead before action streaming):
#define F1WF 16640      // f1w 64 rows stride 132  (dead after fc1)
#define F2WF 25088      // f2w 64 rows stride 196  (dead after fc2)
#define F3WF 37632      // f3w 32 rows stride 68   (in WB1 upper part)
#define ZF   39808      // z   64 rows stride 68
#define Z2F  44160      // z2  64 rows stride 68
#define PF1B 49920
#define PF2B 49984
#define PF3B 50048
#define PB1  50080
#define PB2  50336
#define PW3  50592
#define PB3  50848
#define SMACT 50852     // 64 action partials
#define MSGR 50916      // fc3 raw out, 64 rows stride 36
#define SMEMF (MSGR + 64*36)
#define SMEMB (SMEMF*4)

// pre-rounded (tf32-rna) weights in device scratch
#define GF1 0
#define GF2 8192
#define GF3 20480
#define GW1 22528
#define GW2 88064
__device__ __align__(16) float g_wr[153600];

__device__ __forceinline__ float rt(float x){
    uint32_t u; asm("cvt.rna.tf32.f32 %0, %1;" : "=r"(u) : "f"(x));
    return __uint_as_float(u);
}
__device__ __forceinline__ uint32_t smem_u32(const void* p){
    uint32_t a;
    asm("{ .reg .u64 t; cvta.to.shared.u64 t, %1; cvt.u32.u64 %0, t; }" : "=r"(a) : "l"(p));
    return a;
}
__device__ __forceinline__ void mma8(float* d, uint32_t a0,uint32_t a1,uint32_t a2,uint32_t a3,
                                     uint32_t b0,uint32_t b1){
    asm("mma.sync.aligned.m16n8k8.row.col.f32.tf32.tf32.f32 "
        "{%0,%1,%2,%3},{%4,%5,%6,%7},{%8,%9},{%0,%1,%2,%3};"
        : "+f"(d[0]),"+f"(d[1]),"+f"(d[2]),"+f"(d[3])
        : "r"(a0),"r"(a1),"r"(a2),"r"(a3),"r"(b0),"r"(b1));
}
// m16 x (NS*8) tile, K=KS*8. A stride AS, W stride WS (both % 32 == 4 -> conflict-free)
template<int KS,int NS,int AS,int WS>
__device__ __forceinline__ void mt(float (&acc)[4][4], const float* A, const float* W){
    const int lane = threadIdx.x & 31, g = lane >> 2, l4 = lane & 3;
    const uint32_t* a = (const uint32_t*)(A + g*AS + l4);
    const uint32_t* w = (const uint32_t*)(W + g*WS + l4);
    #pragma unroll 8
    for (int k = 0; k < KS; k++) {
        uint32_t a0=a[0], a1=a[8*AS], a2=a[4], a3=a[8*AS+4];
        #pragma unroll
        for (int n = 0; n < NS; n++)
            mma8(acc[n], a0,a1,a2,a3, w[n*8*WS], w[n*8*WS+4]);
        a += 8; w += 8;
    }
}
// m32n32, K=256, both strides 260 (action layers)
__device__ __forceinline__ void chunk_mma(float (&acc)[2][4][4], const float* A, const float* W){
    const int lane = threadIdx.x & 31, g = lane >> 2, l4 = lane & 3;
    const uint32_t* a = (const uint32_t*)(A + g*260 + l4);
    const uint32_t* w = (const uint32_t*)(W + g*260 + l4);
    #pragma unroll 8
    for (int k = 0; k < 32; k++) {
        uint32_t a00=a[0],      a01=a[8*260],  a02=a[4],        a03=a[8*260+4];
        uint32_t a10=a[16*260], a11=a[24*260], a12=a[16*260+4], a13=a[24*260+4];
        #pragma unroll
        for (int n = 0; n < 4; n++) {
            uint32_t b0 = w[n*8*260], b1 = w[n*8*260+4];
            mma8(acc[0][n], a00,a01,a02,a03, b0,b1);
            mma8(acc[1][n], a10,a11,a12,a13, b0,b1);
        }
        a += 8; w += 8;
    }
}
// loader warps: 64x256 chunk (already tf32-rounded) -> padded smem via cp.async
__device__ __forceinline__ void ld64x256(uint32_t sdst, const float* gsrc, int lt){
    #pragma unroll 4
    for (int i = 0; i < 32; i++) {
        int q = lt + i*128;
        int row = q >> 6, c4 = q & 63;
        uint32_t d = sdst + (uint32_t)(row*260 + c4*4)*4u;
        asm volatile("cp.async.cg.shared.global [%0], [%1], 16;" :: "r"(d), "l"(gsrc + q*4));
    }
    asm volatile("cp.async.commit_group;" ::: "memory");
    asm volatile("cp.async.wait_group 0;" ::: "memory");
}

__global__ void prep_weights(const float* f1w, const float* f2w, const float* f3w,
                             const float* w1, const float* w2){
    int i = blockIdx.x*blockDim.x + threadIdx.x, n = gridDim.x*blockDim.x;
    for (int k=i; k<8192;  k+=n) g_wr[GF1+k] = rt(f1w[k]);
    for (int k=i; k<12288; k+=n) g_wr[GF2+k] = rt(f2w[k]);
    for (int k=i; k<2048;  k+=n) g_wr[GF3+k] = rt(f3w[k]);
    for (int k=i; k<65536; k+=n) g_wr[GW1+k] = rt(w1[k]);
    for (int k=i; k<65536; k+=n) g_wr[GW2+k] = rt(w2[k]);
}

__global__ void __launch_bounds__(256, 1)
actor_kernel(const float* __restrict__ x,  const float* __restrict__ m,
             const float* __restrict__ f1b, const float* __restrict__ f2b,
             const float* __restrict__ f3b,
             const float* __restrict__ b1,  const float* __restrict__ b2,
             const float* __restrict__ w3,  const float* __restrict__ b3,
             float* __restrict__ out, int Bn)
{
    extern __shared__ float sm[];
    const uint32_t sbu = smem_u32(sm);
    const int tid = threadIdx.x, wid = tid >> 5, lane = tid & 31;
    const int g = lane >> 2, l4 = lane & 3;
    const long r0 = (long)blockIdx.x * 64;
    const int lt = tid - 128;                     // loader thread idx (warps 4-7)
    const float* gw1 = g_wr + GW1;
    const float* gw2 = g_wr + GW2;

    // ---------------- P0: params, inputs, msg weights ----------------
    if (tid < 64) { sm[PF1B+tid]=f1b[tid]; sm[PF2B+tid]=f2b[tid]; sm[SMACT+tid]=0.f; }
    if (tid < 32) sm[PF3B+tid]=f3b[tid];
    sm[PB1+tid]=b1[tid]; sm[PB2+tid]=b2[tid]; sm[PW3+tid]=w3[tid];
    if (tid == 0) sm[PB3]=b3[0];
    {
        const float4* x4 = (const float4*)(x + r0*128);
        const float4* m4 = (const float4*)(m + r0*128);
        #pragma unroll 4
        for (int i = 0; i < 8; i++) {
            int q = tid + i*256, row = q >> 5, c4 = q & 31;
            float4 v = x4[q];
            v.x=rt(v.x); v.y=rt(v.y); v.z=rt(v.z); v.w=rt(v.w);
            *(float4*)&sm[XMF + row*260 + c4*4] = v;
            float4 u = m4[q];
            u.x=rt(tanhf(u.x)); u.y=rt(tanhf(u.y)); u.z=rt(tanhf(u.z)); u.w=rt(tanhf(u.w));
            *(float4*)&sm[XMF + row*260 + 128 + c4*4] = u;
        }
        const float4* s1 = (const float4*)(g_wr + GF1);
        #pragma unroll 4
        for (int q = tid; q < 2048; q += 256) {
            int row = q >> 5, c4 = q & 31;
            *(float4*)&sm[F1WF + row*132 + c4*4] = s1[q];
        }
        const float4* s2 = (const float4*)(g_wr + GF2);
        #pragma unroll 4
        for (int q = tid; q < 3072; q += 256) {
            int row = q / 48, c4 = q - row*48;
            *(float4*)&sm[F2WF + row*196 + c4*4] = s2[q];
        }
        const float4* s3 = (const float4*)(g_wr + GF3);
        for (int q = tid; q < 512; q += 256) {
            int row = q >> 4, c4 = q & 15;
            *(float4*)&sm[F3WF + row*68 + c4*4] = s3[q];
        }
    }
    __syncthreads();

    // ---------------- P1: fc1 [64x64], K=128 (all 8 warps, m16n32) ----------------
    {
        const int rb = (wid >> 1) * 16, nb = (wid & 1) * 32;
        float ac[4][4] = {};
        mt<16,4,260,132>(ac, sm + XMF + rb*260, sm + F1WF + nb*132);
        #pragma unroll
        for (int n = 0; n < 4; n++) {
            int cb = nb + n*8 + 2*l4, r = rb + g;
            sm[ZF + r*68 + cb]       = ac[n][0] + sm[PF1B+cb];
            sm[ZF + r*68 + cb+1]     = ac[n][1] + sm[PF1B+cb+1];
            sm[ZF + (r+8)*68 + cb]   = ac[n][2] + sm[PF1B+cb];
            sm[ZF + (r+8)*68 + cb+1] = ac[n][3] + sm[PF1B+cb+1];
        }
    }
    __syncthreads();

    // ---------------- P2: fc1 epilogue (l2norm+tanh) + tanh(x) in place ----------------
    {
        int row = tid >> 2, sg = tid & 3;
        float4 q0 = *(float4*)&sm[ZF + row*68 + sg*16];
        float4 q1 = *(float4*)&sm[ZF + row*68 + sg*16 + 4];
        float4 q2 = *(float4*)&sm[ZF + row*68 + sg*16 + 8];
        float4 q3 = *(float4*)&sm[ZF + row*68 + sg*16 + 12];
        float ss = q0.x*q0.x+q0.y*q0.y+q0.z*q0.z+q0.w*q0.w
                 + q1.x*q1.x+q1.y*q1.y+q1.z*q1.z+q1.w*q1.w
                 + q2.x*q2.x+q2.y*q2.y+q2.z*q2.z+q2.w*q2.w
                 + q3.x*q3.x+q3.y*q3.y+q3.z*q3.z+q3.w*q3.w;
        ss += __shfl_xor_sync(~0u, ss, 1);
        ss += __shfl_xor_sync(~0u, ss, 2);
        float inv = 1.0f / fmaxf(sqrtf(ss), 1e-12f);
        q0.x=rt(tanhf(q0.x*inv)); q0.y=rt(tanhf(q0.y*inv)); q0.z=rt(tanhf(q0.z*inv)); q0.w=rt(tanhf(q0.w*inv));
        q1.x=rt(tanhf(q1.x*inv)); q1.y=rt(tanhf(q1.y*inv)); q1.z=rt(tanhf(q1.z*inv)); q1.w=rt(tanhf(q1.w*inv));
        q2.x=rt(tanhf(q2.x*inv)); q2.y=rt(tanhf(q2.y*inv)); q2.z=rt(tanhf(q2.z*inv)); q2.w=rt(tanhf(q2.w*inv));
        q3.x=rt(tanhf(q3.x*inv)); q3.y=rt(tanhf(q3.y*inv)); q3.z=rt(tanhf(q3.z*inv)); q3.w=rt(tanhf(q3.w*inv));
        *(float4*)&sm[ZF + row*68 + sg*16]      = q0;
        *(float4*)&sm[ZF + row*68 + sg*16 + 4]  = q1;
        *(float4*)&sm[ZF + row*68 + sg*16 + 8]  = q2;
        *(float4*)&sm[ZF + row*68 + sg*16 + 12] = q3;
        #pragma unroll 4
        for (int i = 0; i < 8; i++) {
            int q = tid + i*256, r = q >> 5, c4 = q & 31;
            float4* p = (float4*)&sm[XMF + r*260 + c4*4];
            float4 v = *p;
            v.x=rt(tanhf(v.x)); v.y=rt(tanhf(v.y)); v.z=rt(tanhf(v.z)); v.w=rt(tanhf(v.w));
            *p = v;
        }
    }
    __syncthreads();

    // ---------------- P3: fc2 [64x64], K=192 = [z | tanh(m)] ----------------
    {
        const int rb = (wid >> 1) * 16, nb = (wid & 1) * 32;
        float ac[4][4] = {};
        mt<8,4,68,196>(ac, sm + ZF + rb*68, sm + F2WF + nb*196);
        mt<16,4,260,196>(ac, sm + XMF + rb*260 + 128, sm + F2WF + nb*196 + 64);
        #pragma unroll
        for (int n = 0; n < 4; n++) {
            int cb = nb + n*8 + 2*l4, r = rb + g;
            sm[Z2F + r*68 + cb]       = rt(tanhf(ac[n][0] + sm[PF2B+cb]));
            sm[Z2F + r*68 + cb+1]     = rt(tanhf(ac[n][1] + sm[PF2B+cb+1]));
            sm[Z2F + (r+8)*68 + cb]   = rt(tanhf(ac[n][2] + sm[PF2B+cb]));
            sm[Z2F + (r+8)*68 + cb+1] = rt(tanhf(ac[n][3] + sm[PF2B+cb+1]));
        }
    }
    __syncthreads();

    // ---------------- P4: fc3 (warps 0-3) || cp.async w1 chunk0 (warps 4-7) ----------------
    if (wid < 4) {
        const int rb = wid * 16;
        float ac[4][4] = {};
        mt<8,4,68,68>(ac, sm + Z2F + rb*68, sm + F3WF);
        #pragma unroll
        for (int n = 0; n < 4; n++) {
            int cb = n*8 + 2*l4, r = rb + g;
            sm[MSGR + r*36 + cb]       = ac[n][0] + sm[PF3B+cb];
            sm[MSGR + r*36 + cb+1]     = ac[n][1] + sm[PF3B+cb+1];
            sm[MSGR + (r+8)*36 + cb]   = ac[n][2] + sm[PF3B+cb];
            sm[MSGR + (r+8)*36 + cb+1] = ac[n][3] + sm[PF3B+cb+1];
        }
    } else {
        ld64x256(sbu + WB0F*4, gw1, lt);
    }
    __syncthreads();

    // ---------------- P5: fc3 epilogue (l2norm -> msg out) || w1 chunk1 ----------------
    if (tid < 128) {
        int row = tid >> 1, sg = tid & 1;
        float4 q0 = *(float4*)&sm[MSGR + row*36 + sg*16];
        float4 q1 = *(float4*)&sm[MSGR + row*36 + sg*16 + 4];
        float4 q2 = *(float4*)&sm[MSGR + row*36 + sg*16 + 8];
        float4 q3 = *(float4*)&sm[MSGR + row*36 + sg*16 + 12];
        float ss = q0.x*q0.x+q0.y*q0.y+q0.z*q0.z+q0.w*q0.w
                 + q1.x*q1.x+q1.y*q1.y+q1.z*q1.z+q1.w*q1.w
                 + q2.x*q2.x+q2.y*q2.y+q2.z*q2.z+q2.w*q2.w
                 + q3.x*q3.x+q3.y*q3.y+q3.z*q3.z+q3.w*q3.w;
        ss += __shfl_xor_sync(~0u, ss, 1);
        float inv = 1.0f / fmaxf(sqrtf(ss), 1e-12f);
        float4* og = (float4*)(out + (r0 + row)*32 + sg*16);
        og[0] = make_float4(q0.x*inv, q0.y*inv, q0.z*inv, q0.w*inv);
        og[1] = make_float4(q1.x*inv, q1.y*inv, q1.z*inv, q1.w*inv);
        og[2] = make_float4(q2.x*inv, q2.y*inv, q2.z*inv, q2.w*inv);
        og[3] = make_float4(q3.x*inv, q3.y*inv, q3.z*inv, q3.w*inv);
    } else {
        ld64x256(sbu + WB1F*4, gw1 + 16384, lt);
    }
    __syncthreads();

    // ---------------- action L1: h1 in registers, chunks double-buffered ----------------
    const int rbase = (wid >> 1) * 32;          // compute warps 0-3
    const int nh32 = (wid & 1) * 32;
    float hr[4][2][4][4];
    #pragma unroll
    for (int st = 0; st < 4; st++) {
        if (wid < 4) {
            #pragma unroll
            for (int t = 0; t < 2; t++)
                #pragma unroll
                for (int n = 0; n < 4; n++)
                    hr[st][t][n][0]=hr[st][t][n][1]=hr[st][t][n][2]=hr[st][t][n][3]=0.f;
            chunk_mma(hr[st], sm + XMF + rbase*260,
                      sm + ((st & 1) ? WB1F : WB0F) + nh32*260);
        } else if (st >= 1) {
            const float* src = (st < 3) ? (gw1 + (st+1)*16384) : gw2;
            ld64x256(sbu + (((st+1) & 1) ? WB1F : WB0F)*4, src, lt);
        }
        __syncthreads();
    }
    // h1 -> XM (relu+bias+rt) || loaders: w2 chunk1 -> WB1
    if (wid < 4) {
        #pragma unroll
        for (int c = 0; c < 4; c++)
            #pragma unroll
            for (int t = 0; t < 2; t++)
                #pragma unroll
                for (int n = 0; n < 4; n++) {
                    int gc = c*64 + nh32 + n*8 + 2*l4;
                    int r = rbase + 16*t + g;
                    float ba = sm[PB1+gc], bb = sm[PB1+gc+1];
                    sm[XMF + r*260 + gc]       = rt(fmaxf(hr[c][t][n][0] + ba, 0.f));
                    sm[XMF + r*260 + gc+1]     = rt(fmaxf(hr[c][t][n][1] + bb, 0.f));
                    sm[XMF + (r+8)*260 + gc]   = rt(fmaxf(hr[c][t][n][2] + ba, 0.f));
                    sm[XMF + (r+8)*260 + gc+1] = rt(fmaxf(hr[c][t][n][3] + bb, 0.f));
                }
    } else {
        ld64x256(sbu + WB1F*4, gw2 + 16384, lt);
    }
    __syncthreads();

    // ---------------- action L2: fused w3 dot, h2 never stored ----------------
    float pr0 = 0.f, pr1 = 0.f, pr2 = 0.f, pr3 = 0.f;
    #pragma unroll
    for (int st = 0; st < 4; st++) {
        if (wid < 4) {
            float ac[2][4][4] = {};
            chunk_mma(ac, sm + XMF + rbase*260,
                      sm + ((st & 1) ? WB1F : WB0F) + nh32*260);
            #pragma unroll
            for (int t = 0; t < 2; t++)
                #pragma unroll
                for (int n = 0; n < 4; n++) {
                    int gc = st*64 + nh32 + n*8 + 2*l4;
                    float ba = sm[PB2+gc], bb = sm[PB2+gc+1];
                    float wa = sm[PW3+gc], wb = sm[PW3+gc+1];
                    float p0 = fmaxf(ac[t][n][0]+ba,0.f)*wa + fmaxf(ac[t][n][1]+bb,0.f)*wb;
                    float p1 = fmaxf(ac[t][n][2]+ba,0.f)*wa + fmaxf(ac[t][n][3]+bb,0.f)*wb;
                    if (t == 0) { pr0 += p0; pr1 += p1; }
                    else        { pr2 += p0; pr3 += p1; }
                }
        } else if (st == 1 || st == 2) {
            ld64x256(sbu + (((st+1) & 1) ? WB1F : WB0F)*4, gw2 + (st+1)*16384, lt);
        }
        __syncthreads();
    }
    if (wid < 4) {
        pr0 += __shfl_xor_sync(~0u, pr0, 1); pr0 += __shfl_xor_sync(~0u, pr0, 2);
        pr1 += __shfl_xor_sync(~0u, pr1, 1); pr1 += __shfl_xor_sync(~0u, pr1, 2);
        pr2 += __shfl_xor_sync(~0u, pr2, 1); pr2 += __shfl_xor_sync(~0u, pr2, 2);
        pr3 += __shfl_xor_sync(~0u, pr3, 1); pr3 += __shfl_xor_sync(~0u, pr3, 2);
        if (l4 == 0) {
            atomicAdd(&sm[SMACT + rbase + g],      pr0);
            atomicAdd(&sm[SMACT + rbase + g + 8],  pr1);
            atomicAdd(&sm[SMACT + rbase + g + 16], pr2);
            atomicAdd(&sm[SMACT + rbase + g + 24], pr3);
        }
    }
    __syncthreads();
    if (tid < 64)
        out[(long)Bn*32 + r0 + tid] = tanhf(sm[SMACT+tid] + sm[PB3]);
}

extern "C" void kernel_launch(void* const* d_in, const int* in_sizes, int n_in,
                              void* d_out, int out_size) {
    const float* x   = (const float*)d_in[0];
    const float* m   = (const float*)d_in[1];
    const float* f1w = (const float*)d_in[2];
    const float* f1b = (const float*)d_in[3];
    const float* f2w = (const float*)d_in[4];
    const float* f2b = (const float*)d_in[5];
    const float* f3w = (const float*)d_in[6];
    const float* f3b = (const float*)d_in[7];
    const float* w1  = (const float*)d_in[8];
    const float* b1  = (const float*)d_in[9];
    const float* w2  = (const float*)d_in[10];
    const float* b2  = (const float*)d_in[11];
    const float* w3  = (const float*)d_in[12];
    const float* b3  = (const float*)d_in[13];
    float* out = (float*)d_out;

    int Bn = in_sizes[0] / 128;
    prep_weights<<<128, 256>>>(f1w, f2w, f3w, w1, w2);
    cudaFuncSetAttribute(actor_kernel, cudaFuncAttributeMaxDynamicSharedMemorySize, SMEMB);
    actor_kernel<<<Bn / 64, 256, SMEMB>>>(x, m, f1b, f2b, f3b,
                                          b1, b2, w3, b3, out, Bn);
}

// round 12
// speedup vs baseline: 1.4497x; 1.0271x over previous
#include <cuda_runtime.h>
#include <cstdint>

// ---------------- smem float offsets ----------------
#define XMF 0                 // 64 x 260 activation plane (x|tanh(m), later h1)
#define RB  16640             // buffer region: 8 chunks of 32x132
#define BUF(i) (RB + (i)*4224)
#define F1W RB                // 64x132 (dead after P1)
#define F2W (RB+8448)         // 64x196 (dead after P3)
#define F3W (RB+20992)        // 32x68  (dead after P4)
#define ZZ  (RB+23168)        // 64x68  (dead after P3)
#define Z2  (RB+27520)        // 64x68  (dead after P4)
#define MSGR (RB+16896)       // 64x36  (written P4, read P5; inside dead f2w / b4-5)
#define PF1B 50432
#define PF2B 50496
#define PF3B 50560
#define PB1  50592
#define PB2  50848
#define PW3  51104
#define PB3  51360
#define SMACT 51364
#define SMEMF 51428
#define SMEMB (SMEMF*4)

// pre-rounded (tf32-rna) weights in device scratch
#define GF1 0
#define GF2 8192
#define GF3 20480
#define GW1 22528
#define GW2 88064
__device__ __align__(16) float g_wr[153600];

__device__ __forceinline__ float rt(float x){
    uint32_t u; asm("cvt.rna.tf32.f32 %0, %1;" : "=r"(u) : "f"(x));
    return __uint_as_float(u);
}
__device__ __forceinline__ uint32_t smem_u32(const void* p){
    uint32_t a;
    asm("{ .reg .u64 t; cvta.to.shared.u64 t, %1; cvt.u32.u64 %0, t; }" : "=r"(a) : "l"(p));
    return a;
}
__device__ __forceinline__ void mma8(float* d, uint32_t a0,uint32_t a1,uint32_t a2,uint32_t a3,
                                     uint32_t b0,uint32_t b1){
    asm("mma.sync.aligned.m16n8k8.row.col.f32.tf32.tf32.f32 "
        "{%0,%1,%2,%3},{%4,%5,%6,%7},{%8,%9},{%0,%1,%2,%3};"
        : "+f"(d[0]),"+f"(d[1]),"+f"(d[2]),"+f"(d[3])
        : "r"(a0),"r"(a1),"r"(a2),"r"(a3),"r"(b0),"r"(b1));
}
// msg-branch tile: m16 x (NS*8), K=KS*8, strides AS/WS (% 32 == 4)
template<int KS,int NS,int AS,int WS>
__device__ __forceinline__ void mt(float (&acc)[4][4], const float* A, const float* W){
    const int lane = threadIdx.x & 31, g = lane >> 2, l4 = lane & 3;
    const uint32_t* a = (const uint32_t*)(A + g*AS + l4);
    const uint32_t* w = (const uint32_t*)(W + g*WS + l4);
    #pragma unroll 8
    for (int k = 0; k < KS; k++) {
        uint32_t a0=a[0], a1=a[8*AS], a2=a[4], a3=a[8*AS+4];
        #pragma unroll
        for (int n = 0; n < NS; n++)
            mma8(acc[n], a0,a1,a2,a3, w[n*8*WS], w[n*8*WS+4]);
        a += 8; w += 8;
    }
}
// action tile: m64 x n32, K=128. A stride 260, W (chunk buffer) stride 132.
__device__ __forceinline__ void mma64(float (&acc)[4][4][4], const float* A, const float* W){
    const int lane = threadIdx.x & 31, g = lane >> 2, l4 = lane & 3;
    const uint32_t* a = (const uint32_t*)(A + g*260 + l4);
    const uint32_t* w = (const uint32_t*)(W + g*132 + l4);
    #pragma unroll 4
    for (int k = 0; k < 16; k++) {
        uint32_t av[4][4];
        #pragma unroll
        for (int s = 0; s < 4; s++) {
            av[s][0]=a[s*16*260]; av[s][1]=a[(s*16+8)*260];
            av[s][2]=a[s*16*260+4]; av[s][3]=a[(s*16+8)*260+4];
        }
        #pragma unroll
        for (int t = 0; t < 4; t++) {
            uint32_t b0 = w[t*8*132], b1 = w[t*8*132+4];
            #pragma unroll
            for (int s = 0; s < 4; s++)
                mma8(acc[s][t], av[s][0],av[s][1],av[s][2],av[s][3], b0,b1);
        }
        a += 8; w += 8;
    }
}
// one warp loads one 32x128 chunk (row stride 256 in gmem) into a 32x132 buffer
__device__ __forceinline__ void ldchunk(uint32_t sdst, const float* g, int lane){
    #pragma unroll 8
    for (int i = 0; i < 32; i++) {
        uint32_t d = sdst + (uint32_t)(i*132 + lane*4)*4u;
        asm volatile("cp.async.cg.shared.global [%0], [%1], 16;" :: "r"(d), "l"(g + i*256 + lane*4));
    }
    asm volatile("cp.async.commit_group;" ::: "memory");
    asm volatile("cp.async.wait_group 0;" ::: "memory");
}

__global__ void prep_weights(const float* f1w, const float* f2w, const float* f3w,
                             const float* w1, const float* w2){
    int i = blockIdx.x*blockDim.x + threadIdx.x, n = gridDim.x*blockDim.x;
    for (int k=i; k<8192;  k+=n) g_wr[GF1+k] = rt(f1w[k]);
    for (int k=i; k<12288; k+=n) g_wr[GF2+k] = rt(f2w[k]);
    for (int k=i; k<2048;  k+=n) g_wr[GF3+k] = rt(f3w[k]);
    for (int k=i; k<65536; k+=n) g_wr[GW1+k] = rt(w1[k]);
    for (int k=i; k<65536; k+=n) g_wr[GW2+k] = rt(w2[k]);
}

__global__ void __launch_bounds__(256, 1)
actor_kernel(const float* __restrict__ x,  const float* __restrict__ m,
             const float* __restrict__ f1b, const float* __restrict__ f2b,
             const float* __restrict__ f3b,
             const float* __restrict__ b1,  const float* __restrict__ b2,
             const float* __restrict__ w3,  const float* __restrict__ b3,
             float* __restrict__ out, int Bn)
{
    extern __shared__ float sm[];
    const uint32_t sbu = smem_u32(sm);
    const int tid = threadIdx.x, wid = tid >> 5, lane = tid & 31;
    const int g = lane >> 2, l4 = lane & 3;
    const long r0 = (long)blockIdx.x * 64;
    const float* gw1 = g_wr + GW1;
    const float* gw2 = g_wr + GW2;

    // ---------------- P0: params, inputs, msg weights ----------------
    if (tid < 64) { sm[PF1B+tid]=f1b[tid]; sm[PF2B+tid]=f2b[tid]; sm[SMACT+tid]=0.f; }
    if (tid < 32) sm[PF3B+tid]=f3b[tid];
    sm[PB1+tid]=b1[tid]; sm[PB2+tid]=b2[tid]; sm[PW3+tid]=w3[tid];
    if (tid == 0) sm[PB3]=b3[0];
    {
        const float4* x4 = (const float4*)(x + r0*128);
        const float4* m4 = (const float4*)(m + r0*128);
        #pragma unroll 4
        for (int i = 0; i < 8; i++) {
            int q = tid + i*256, row = q >> 5, c4 = q & 31;
            float4 v = x4[q];
            v.x=rt(v.x); v.y=rt(v.y); v.z=rt(v.z); v.w=rt(v.w);
            *(float4*)&sm[XMF + row*260 + c4*4] = v;
            float4 u = m4[q];
            u.x=rt(tanhf(u.x)); u.y=rt(tanhf(u.y)); u.z=rt(tanhf(u.z)); u.w=rt(tanhf(u.w));
            *(float4*)&sm[XMF + row*260 + 128 + c4*4] = u;
        }
        const float4* s1 = (const float4*)(g_wr + GF1);
        #pragma unroll 4
        for (int q = tid; q < 2048; q += 256) {
            int row = q >> 5, c4 = q & 31;
            *(float4*)&sm[F1W + row*132 + c4*4] = s1[q];
        }
        const float4* s2 = (const float4*)(g_wr + GF2);
        #pragma unroll 4
        for (int q = tid; q < 3072; q += 256) {
            int row = q / 48, c4 = q - row*48;
            *(float4*)&sm[F2W + row*196 + c4*4] = s2[q];
        }
        const float4* s3 = (const float4*)(g_wr + GF3);
        for (int q = tid; q < 512; q += 256) {
            int row = q >> 4, c4 = q & 15;
            *(float4*)&sm[F3W + row*68 + c4*4] = s3[q];
        }
    }
    __syncthreads();

    // ---------------- P1: fc1 [64x64], K=128, all 8 warps m16n32 ----------------
    {
        const int rb = (wid >> 1) * 16, nb = (wid & 1) * 32;
        float ac[4][4] = {};
        mt<16,4,260,132>(ac, sm + XMF + rb*260, sm + F1W + nb*132);
        #pragma unroll
        for (int n = 0; n < 4; n++) {
            int cb = nb + n*8 + 2*l4, r = rb + g;
            sm[ZZ + r*68 + cb]       = ac[n][0] + sm[PF1B+cb];
            sm[ZZ + r*68 + cb+1]     = ac[n][1] + sm[PF1B+cb+1];
            sm[ZZ + (r+8)*68 + cb]   = ac[n][2] + sm[PF1B+cb];
            sm[ZZ + (r+8)*68 + cb+1] = ac[n][3] + sm[PF1B+cb+1];
        }
    }
    __syncthreads();

    // ---------------- P2: z l2norm+tanh ; tanh(x) in place ----------------
    {
        int row = tid >> 2, sg = tid & 3;
        float4 q0 = *(float4*)&sm[ZZ + row*68 + sg*16];
        float4 q1 = *(float4*)&sm[ZZ + row*68 + sg*16 + 4];
        float4 q2 = *(float4*)&sm[ZZ + row*68 + sg*16 + 8];
        float4 q3 = *(float4*)&sm[ZZ + row*68 + sg*16 + 12];
        float ss = q0.x*q0.x+q0.y*q0.y+q0.z*q0.z+q0.w*q0.w
                 + q1.x*q1.x+q1.y*q1.y+q1.z*q1.z+q1.w*q1.w
                 + q2.x*q2.x+q2.y*q2.y+q2.z*q2.z+q2.w*q2.w
                 + q3.x*q3.x+q3.y*q3.y+q3.z*q3.z+q3.w*q3.w;
        ss += __shfl_xor_sync(~0u, ss, 1);
        ss += __shfl_xor_sync(~0u, ss, 2);
        float inv = 1.0f / fmaxf(sqrtf(ss), 1e-12f);
        q0.x=rt(tanhf(q0.x*inv)); q0.y=rt(tanhf(q0.y*inv)); q0.z=rt(tanhf(q0.z*inv)); q0.w=rt(tanhf(q0.w*inv));
        q1.x=rt(tanhf(q1.x*inv)); q1.y=rt(tanhf(q1.y*inv)); q1.z=rt(tanhf(q1.z*inv)); q1.w=rt(tanhf(q1.w*inv));
        q2.x=rt(tanhf(q2.x*inv)); q2.y=rt(tanhf(q2.y*inv)); q2.z=rt(tanhf(q2.z*inv)); q2.w=rt(tanhf(q2.w*inv));
        q3.x=rt(tanhf(q3.x*inv)); q3.y=rt(tanhf(q3.y*inv)); q3.z=rt(tanhf(q3.z*inv)); q3.w=rt(tanhf(q3.w*inv));
        *(float4*)&sm[ZZ + row*68 + sg*16]      = q0;
        *(float4*)&sm[ZZ + row*68 + sg*16 + 4]  = q1;
        *(float4*)&sm[ZZ + row*68 + sg*16 + 8]  = q2;
        *(float4*)&sm[ZZ + row*68 + sg*16 + 12] = q3;
        #pragma unroll 4
        for (int i = 0; i < 8; i++) {
            int q = tid + i*256, r = q >> 5, c4 = q & 31;
            float4* p = (float4*)&sm[XMF + r*260 + c4*4];
            float4 v = *p;
            v.x=rt(tanhf(v.x)); v.y=rt(tanhf(v.y)); v.z=rt(tanhf(v.z)); v.w=rt(tanhf(v.w));
            *p = v;
        }
    }
    __syncthreads();

    // ---------------- P3: fc2 [64x64], K=192 = [z | tanh(m)] ----------------
    {
        const int rb = (wid >> 1) * 16, nb = (wid & 1) * 32;
        float ac[4][4] = {};
        mt<8,4,68,196>(ac, sm + ZZ + rb*68, sm + F2W + nb*196);
        mt<16,4,260,196>(ac, sm + XMF + rb*260 + 128, sm + F2W + nb*196 + 64);
        #pragma unroll
        for (int n = 0; n < 4; n++) {
            int cb = nb + n*8 + 2*l4, r = rb + g;
            sm[Z2 + r*68 + cb]       = rt(tanhf(ac[n][0] + sm[PF2B+cb]));
            sm[Z2 + r*68 + cb+1]     = rt(tanhf(ac[n][1] + sm[PF2B+cb+1]));
            sm[Z2 + (r+8)*68 + cb]   = rt(tanhf(ac[n][2] + sm[PF2B+cb]));
            sm[Z2 + (r+8)*68 + cb+1] = rt(tanhf(ac[n][3] + sm[PF2B+cb+1]));
        }
    }
    __syncthreads();

    const int myn = wid & 3;
    const bool gA = wid < 4;

    // ---------------- P4: fc3 (w0-3) || preload L1(n0-3,k0) -> b0-3 (w4-7) ----------------
    if (gA) {
        const int rb = wid * 16;
        float ac[4][4] = {};
        mt<8,4,68,68>(ac, sm + Z2 + rb*68, sm + F3W);
        #pragma unroll
        for (int n = 0; n < 4; n++) {
            int cb = n*8 + 2*l4, r = rb + g;
            sm[MSGR + r*36 + cb]       = ac[n][0] + sm[PF3B+cb];
            sm[MSGR + r*36 + cb+1]     = ac[n][1] + sm[PF3B+cb+1];
            sm[MSGR + (r+8)*36 + cb]   = ac[n][2] + sm[PF3B+cb];
            sm[MSGR + (r+8)*36 + cb+1] = ac[n][3] + sm[PF3B+cb+1];
        }
    } else {
        ldchunk(sbu + BUF(myn)*4, gw1 + myn*8192, lane);
    }
    __syncthreads();

    // ---------------- P5: msg l2norm -> out (tid<128) ----------------
    if (tid < 128) {
        int row = tid >> 1, sg = tid & 1;
        float4 q0 = *(float4*)&sm[MSGR + row*36 + sg*16];
        float4 q1 = *(float4*)&sm[MSGR + row*36 + sg*16 + 4];
        float4 q2 = *(float4*)&sm[MSGR + row*36 + sg*16 + 8];
        float4 q3 = *(float4*)&sm[MSGR + row*36 + sg*16 + 12];
        float ss = q0.x*q0.x+q0.y*q0.y+q0.z*q0.z+q0.w*q0.w
                 + q1.x*q1.x+q1.y*q1.y+q1.z*q1.z+q1.w*q1.w
                 + q2.x*q2.x+q2.y*q2.y+q2.z*q2.z+q2.w*q2.w
                 + q3.x*q3.x+q3.y*q3.y+q3.z*q3.z+q3.w*q3.w;
        ss += __shfl_xor_sync(~0u, ss, 1);
        float inv = 1.0f / fmaxf(sqrtf(ss), 1e-12f);
        float4* og = (float4*)(out + (r0 + row)*32 + sg*16);
        og[0] = make_float4(q0.x*inv, q0.y*inv, q0.z*inv, q0.w*inv);
        og[1] = make_float4(q1.x*inv, q1.y*inv, q1.z*inv, q1.w*inv);
        og[2] = make_float4(q2.x*inv, q2.y*inv, q2.z*inv, q2.w*inv);
        og[3] = make_float4(q3.x*inv, q3.y*inv, q3.z*inv, q3.w*inv);
    }
    __syncthreads();

    // ---------------- action L1: role-swapped K-split pipeline ----------------
    const int nb = myn*32 + (gA ? 0 : 128);   // this warp's h1/h2 column base
    float h1a[4][4][4];
    #pragma unroll
    for (int s = 0; s < 4; s++)
        #pragma unroll
        for (int t = 0; t < 4; t++)
            h1a[s][t][0]=h1a[s][t][1]=h1a[s][t][2]=h1a[s][t][3]=0.f;

    if (gA) mma64(h1a, sm + XMF,       sm + BUF(myn));                 // S1
    else    ldchunk(sbu + BUF(4+myn)*4, gw1 + myn*8192 + 128, lane);
    __syncthreads();
    if (gA) mma64(h1a, sm + XMF + 128, sm + BUF(4+myn));               // S2
    else    ldchunk(sbu + BUF(myn)*4,   gw1 + (4+myn)*8192, lane);
    __syncthreads();
    if (!gA) mma64(h1a, sm + XMF,       sm + BUF(myn));                // S3
    else     ldchunk(sbu + BUF(4+myn)*4, gw1 + (4+myn)*8192 + 128, lane);
    __syncthreads();
    if (!gA) mma64(h1a, sm + XMF + 128, sm + BUF(4+myn));              // S4
    else     ldchunk(sbu + BUF(myn)*4,   gw2 + myn*8192, lane);
    __syncthreads();

    // S5: h1 -> XM (relu + bias + tf32 round); every warp writes its n32 x m64 slab
    #pragma unroll
    for (int s = 0; s < 4; s++)
        #pragma unroll
        for (int t = 0; t < 4; t++) {
            int cb = nb + t*8 + 2*l4, r = s*16 + g;
            float ba = sm[PB1+cb], bb = sm[PB1+cb+1];
            sm[XMF + r*260 + cb]       = rt(fmaxf(h1a[s][t][0] + ba, 0.f));
            sm[XMF + r*260 + cb+1]     = rt(fmaxf(h1a[s][t][1] + bb, 0.f));
            sm[XMF + (r+8)*260 + cb]   = rt(fmaxf(h1a[s][t][2] + ba, 0.f));
            sm[XMF + (r+8)*260 + cb+1] = rt(fmaxf(h1a[s][t][3] + bb, 0.f));
        }
    __syncthreads();

    // ---------------- action L2: fused w3 dot, h2 never stored ----------------
    float pr[8] = {0,0,0,0,0,0,0,0};
    float ac[4][4][4];
    #pragma unroll
    for (int s = 0; s < 4; s++)
        #pragma unroll
        for (int t = 0; t < 4; t++)
            ac[s][t][0]=ac[s][t][1]=ac[s][t][2]=ac[s][t][3]=0.f;

    if (gA) mma64(ac, sm + XMF,       sm + BUF(myn));                  // S6
    else    ldchunk(sbu + BUF(4+myn)*4, gw2 + myn*8192 + 128, lane);
    __syncthreads();
    if (gA) {                                                          // S7
        mma64(ac, sm + XMF + 128, sm + BUF(4+myn));
        #pragma unroll
        for (int s = 0; s < 4; s++)
            #pragma unroll
            for (int t = 0; t < 4; t++) {
                int cb = nb + t*8 + 2*l4;
                float ba = sm[PB2+cb], bb = sm[PB2+cb+1];
                float wa = sm[PW3+cb], wb = sm[PW3+cb+1];
                pr[2*s]   += fmaxf(ac[s][t][0]+ba,0.f)*wa + fmaxf(ac[s][t][1]+bb,0.f)*wb;
                pr[2*s+1] += fmaxf(ac[s][t][2]+ba,0.f)*wa + fmaxf(ac[s][t][3]+bb,0.f)*wb;
            }
    } else {
        ldchunk(sbu + BUF(myn)*4, gw2 + (4+myn)*8192, lane);
    }
    __syncthreads();
    if (!gA) mma64(ac, sm + XMF,       sm + BUF(myn));                 // S8
    else     ldchunk(sbu + BUF(4+myn)*4, gw2 + (4+myn)*8192 + 128, lane);
    __syncthreads();
    if (!gA) {                                                         // S9
        mma64(ac, sm + XMF + 128, sm + BUF(4+myn));
        #pragma unroll
        for (int s = 0; s < 4; s++)
            #pragma unroll
            for (int t = 0; t < 4; t++) {
                int cb = nb + t*8 + 2*l4;
                float ba = sm[PB2+cb], bb = sm[PB2+cb+1];
                float wa = sm[PW3+cb], wb = sm[PW3+cb+1];
                pr[2*s]   += fmaxf(ac[s][t][0]+ba,0.f)*wa + fmaxf(ac[s][t][1]+bb,0.f)*wb;
                pr[2*s+1] += fmaxf(ac[s][t][2]+ba,0.f)*wa + fmaxf(ac[s][t][3]+bb,0.f)*wb;
            }
    }
    // reduce partials over the l4 quad, then across warps via smem atomics
    #pragma unroll
    for (int i = 0; i < 8; i++) {
        pr[i] += __shfl_xor_sync(~0u, pr[i], 1);
        pr[i] += __shfl_xor_sync(~0u, pr[i], 2);
    }
    if (l4 == 0) {
        #pragma unroll
        for (int s = 0; s < 4; s++) {
            atomicAdd(&sm[SMACT + s*16 + g],     pr[2*s]);
            atomicAdd(&sm[SMACT + s*16 + 8 + g], pr[2*s+1]);
        }
    }
    __syncthreads();
    if (tid < 64)
        out[(long)Bn*32 + r0 + tid] = tanhf(sm[SMACT+tid] + sm[PB3]);
}

extern "C" void kernel_launch(void* const* d_in, const int* in_sizes, int n_in,
                              void* d_out, int out_size) {
    const float* x   = (const float*)d_in[0];
    const float* m   = (const float*)d_in[1];
    const float* f1w = (const float*)d_in[2];
    const float* f1b = (const float*)d_in[3];
    const float* f2w = (const float*)d_in[4];
    const float* f2b = (const float*)d_in[5];
    const float* f3w = (const float*)d_in[6];
    const float* f3b = (const float*)d_in[7];
    const float* w1  = (const float*)d_in[8];
    const float* b1  = (const float*)d_in[9];
    const float* w2  = (const float*)d_in[10];
    const float* b2  = (const float*)d_in[11];
    const float* w3  = (const float*)d_in[12];
    const float* b3  = (const float*)d_in[13];
    float* out = (float*)d_out;

    int Bn = in_sizes[0] / 128;
    prep_weights<<<128, 256>>>(f1w, f2w, f3w, w1, w2);
    cudaFuncSetAttribute(actor_kernel, cudaFuncAttributeMaxDynamicSharedMemorySize, SMEMB);
    actor_kernel<<<Bn / 64, 256, SMEMB>>>(x, m, f1b, f2b, f3b,
                                          b1, b2, w3, b3, out, Bn);
}

// round 13
// speedup vs baseline: 1.5555x; 1.0730x over previous
#include <cuda_runtime.h>
#include <cstdint>

// ---------------- smem float offsets ----------------
#define XMF 0                  // 64 x 260 activation plane (x|tanh(m), later h1)
#define RB  16640
#define BUF2(w,s) (RB + ((s)*8+(w))*2176)   // 16 buffers of 32x68
// msg-branch overlays (time-shared with buffer slots; see phase liveness)
#define F1W  16640             // 64x132, dead after P1
#define F2W  25088             // 64x196, dead after P3
#define ZZ   37632             // 64x68,  dead after P3
#define Z2   41984             // 64x68,  dead after P4
#define F3W  46336             // 32x68,  dead after P4
#define MSGR 48512             // 64x36,  dead after P5
#define PF1B 51456
#define PF2B 51520
#define PF3B 51584
#define PB1  51616
#define PB2  51872
#define PW3  52128
#define PB3  52384
#define SMACT 52388
#define SMEMF 52452
#define SMEMB (SMEMF*4)

// pre-rounded (tf32-rna) weights in device scratch
#define GF1 0
#define GF2 8192
#define GF3 20480
#define GW1 22528
#define GW2 88064
__device__ __align__(16) float g_wr[153600];

__device__ __forceinline__ float rt(float x){
    uint32_t u; asm("cvt.rna.tf32.f32 %0, %1;" : "=r"(u) : "f"(x));
    return __uint_as_float(u);
}
__device__ __forceinline__ uint32_t smem_u32(const void* p){
    uint32_t a;
    asm("{ .reg .u64 t; cvta.to.shared.u64 t, %1; cvt.u32.u64 %0, t; }" : "=r"(a) : "l"(p));
    return a;
}
__device__ __forceinline__ void mma8(float* d, uint32_t a0,uint32_t a1,uint32_t a2,uint32_t a3,
                                     uint32_t b0,uint32_t b1){
    asm("mma.sync.aligned.m16n8k8.row.col.f32.tf32.tf32.f32 "
        "{%0,%1,%2,%3},{%4,%5,%6,%7},{%8,%9},{%0,%1,%2,%3};"
        : "+f"(d[0]),"+f"(d[1]),"+f"(d[2]),"+f"(d[3])
        : "r"(a0),"r"(a1),"r"(a2),"r"(a3),"r"(b0),"r"(b1));
}
// msg tile: m16 x (NS*8), K=KS*8, strides AS/WS (% 32 == 4 -> conflict-free)
template<int KS,int NS,int AS,int WS>
__device__ __forceinline__ void mt(float (&acc)[4][4], const float* A, const float* W){
    const int lane = threadIdx.x & 31, g = lane >> 2, l4 = lane & 3;
    const uint32_t* a = (const uint32_t*)(A + g*AS + l4);
    const uint32_t* w = (const uint32_t*)(W + g*WS + l4);
    #pragma unroll 8
    for (int k = 0; k < KS; k++) {
        uint32_t a0=a[0], a1=a[8*AS], a2=a[4], a3=a[8*AS+4];
        #pragma unroll
        for (int n = 0; n < NS; n++)
            mma8(acc[n], a0,a1,a2,a3, w[n*8*WS], w[n*8*WS+4]);
        a += 8; w += 8;
    }
}
// action tile: m64 x n32, K = KS*8. A stride 260 (XM), W stride 68 (chunk buffer).
template<int KS>
__device__ __forceinline__ void mma64k(float (&acc)[4][4][4], const float* A, const float* W){
    const int lane = threadIdx.x & 31, g = lane >> 2, l4 = lane & 3;
    const uint32_t* a = (const uint32_t*)(A + g*260 + l4);
    const uint32_t* w = (const uint32_t*)(W + g*68 + l4);
    #pragma unroll
    for (int k = 0; k < KS; k++) {
        uint32_t av[4][4];
        #pragma unroll
        for (int s = 0; s < 4; s++) {
            av[s][0]=a[s*16*260];   av[s][1]=a[(s*16+8)*260];
            av[s][2]=a[s*16*260+4]; av[s][3]=a[(s*16+8)*260+4];
        }
        #pragma unroll
        for (int t = 0; t < 4; t++) {
            uint32_t b0 = w[t*8*68], b1 = w[t*8*68+4];
            #pragma unroll
            for (int s = 0; s < 4; s++)
                mma8(acc[s][t], av[s][0],av[s][1],av[s][2],av[s][3], b0,b1);
        }
        a += 8; w += 8;
    }
}
// one warp streams a 32(n) x 64(k) quarter (gmem row stride 256) into a 32x68 buffer
__device__ __forceinline__ void ldq(uint32_t sdst, const float* g, int lane){
    #pragma unroll
    for (int i = 0; i < 16; i++) {
        int idx = lane + i*32;
        int row = idx >> 4, seg = idx & 15;
        uint32_t d = sdst + (uint32_t)(row*68 + seg*4)*4u;
        asm volatile("cp.async.cg.shared.global [%0], [%1], 16;"
                     :: "r"(d), "l"(g + row*256 + seg*4));
    }
    asm volatile("cp.async.commit_group;" ::: "memory");
}
#define CPWAIT1() asm volatile("cp.async.wait_group 1;" ::: "memory")
#define CPWAIT0() asm volatile("cp.async.wait_group 0;" ::: "memory")

__global__ void prep_weights(const float* f1w, const float* f2w, const float* f3w,
                             const float* w1, const float* w2){
    int i = blockIdx.x*blockDim.x + threadIdx.x, n = gridDim.x*blockDim.x;
    for (int k=i; k<8192;  k+=n) g_wr[GF1+k] = rt(f1w[k]);
    for (int k=i; k<12288; k+=n) g_wr[GF2+k] = rt(f2w[k]);
    for (int k=i; k<2048;  k+=n) g_wr[GF3+k] = rt(f3w[k]);
    for (int k=i; k<65536; k+=n) g_wr[GW1+k] = rt(w1[k]);
    for (int k=i; k<65536; k+=n) g_wr[GW2+k] = rt(w2[k]);
}

__global__ void __launch_bounds__(256, 1)
actor_kernel(const float* __restrict__ x,  const float* __restrict__ m,
             const float* __restrict__ f1b, const float* __restrict__ f2b,
             const float* __restrict__ f3b,
             const float* __restrict__ b1,  const float* __restrict__ b2,
             const float* __restrict__ w3,  const float* __restrict__ b3,
             float* __restrict__ out, int Bn)
{
    extern __shared__ float sm[];
    const uint32_t sbu = smem_u32(sm);
    const int tid = threadIdx.x, wid = tid >> 5, lane = tid & 31;
    const int g = lane >> 2, l4 = lane & 3;
    const long r0 = (long)blockIdx.x * 64;
    const float* wsl1 = g_wr + GW1 + wid*8192;   // this warp's W1 rows [wid*32, +32)
    const float* wsl2 = g_wr + GW2 + wid*8192;

    // ---------------- P0: params, inputs, msg weights ----------------
    if (tid < 64) { sm[PF1B+tid]=f1b[tid]; sm[PF2B+tid]=f2b[tid]; sm[SMACT+tid]=0.f; }
    if (tid < 32) sm[PF3B+tid]=f3b[tid];
    sm[PB1+tid]=b1[tid]; sm[PB2+tid]=b2[tid]; sm[PW3+tid]=w3[tid];
    if (tid == 0) sm[PB3]=b3[0];
    {
        const float4* x4 = (const float4*)(x + r0*128);
        const float4* m4 = (const float4*)(m + r0*128);
        #pragma unroll 4
        for (int i = 0; i < 8; i++) {
            int q = tid + i*256, row = q >> 5, c4 = q & 31;
            float4 v = x4[q];
            v.x=rt(v.x); v.y=rt(v.y); v.z=rt(v.z); v.w=rt(v.w);
            *(float4*)&sm[XMF + row*260 + c4*4] = v;
            float4 u = m4[q];
            u.x=rt(tanhf(u.x)); u.y=rt(tanhf(u.y)); u.z=rt(tanhf(u.z)); u.w=rt(tanhf(u.w));
            *(float4*)&sm[XMF + row*260 + 128 + c4*4] = u;
        }
        const float4* s1 = (const float4*)(g_wr + GF1);
        #pragma unroll 4
        for (int q = tid; q < 2048; q += 256) {
            int row = q >> 5, c4 = q & 31;
            *(float4*)&sm[F1W + row*132 + c4*4] = s1[q];
        }
        const float4* s2 = (const float4*)(g_wr + GF2);
        #pragma unroll 4
        for (int q = tid; q < 3072; q += 256) {
            int row = q / 48, c4 = q - row*48;
            *(float4*)&sm[F2W + row*196 + c4*4] = s2[q];
        }
        const float4* s3 = (const float4*)(g_wr + GF3);
        for (int q = tid; q < 512; q += 256) {
            int row = q >> 4, c4 = q & 15;
            *(float4*)&sm[F3W + row*68 + c4*4] = s3[q];
        }
    }
    __syncthreads();

    // ---------------- P1: fc1 [64x64], K=128, all 8 warps m16n32 ----------------
    {
        const int rb = (wid >> 1) * 16, nb = (wid & 1) * 32;
        float ac[4][4] = {};
        mt<16,4,260,132>(ac, sm + XMF + rb*260, sm + F1W + nb*132);
        #pragma unroll
        for (int n = 0; n < 4; n++) {
            int cb = nb + n*8 + 2*l4, r = rb + g;
            sm[ZZ + r*68 + cb]       = ac[n][0] + sm[PF1B+cb];
            sm[ZZ + r*68 + cb+1]     = ac[n][1] + sm[PF1B+cb+1];
            sm[ZZ + (r+8)*68 + cb]   = ac[n][2] + sm[PF1B+cb];
            sm[ZZ + (r+8)*68 + cb+1] = ac[n][3] + sm[PF1B+cb+1];
        }
    }
    __syncthreads();

    // ---------------- P2: z l2norm+tanh ; tanh(x) in place ----------------
    {
        int row = tid >> 2, sg = tid & 3;
        float4 q0 = *(float4*)&sm[ZZ + row*68 + sg*16];
        float4 q1 = *(float4*)&sm[ZZ + row*68 + sg*16 + 4];
        float4 q2 = *(float4*)&sm[ZZ + row*68 + sg*16 + 8];
        float4 q3 = *(float4*)&sm[ZZ + row*68 + sg*16 + 12];
        float ss = q0.x*q0.x+q0.y*q0.y+q0.z*q0.z+q0.w*q0.w
                 + q1.x*q1.x+q1.y*q1.y+q1.z*q1.z+q1.w*q1.w
                 + q2.x*q2.x+q2.y*q2.y+q2.z*q2.z+q2.w*q2.w
                 + q3.x*q3.x+q3.y*q3.y+q3.z*q3.z+q3.w*q3.w;
        ss += __shfl_xor_sync(~0u, ss, 1);
        ss += __shfl_xor_sync(~0u, ss, 2);
        float inv = 1.0f / fmaxf(sqrtf(ss), 1e-12f);
        q0.x=rt(tanhf(q0.x*inv)); q0.y=rt(tanhf(q0.y*inv)); q0.z=rt(tanhf(q0.z*inv)); q0.w=rt(tanhf(q0.w*inv));
        q1.x=rt(tanhf(q1.x*inv)); q1.y=rt(tanhf(q1.y*inv)); q1.z=rt(tanhf(q1.z*inv)); q1.w=rt(tanhf(q1.w*inv));
        q2.x=rt(tanhf(q2.x*inv)); q2.y=rt(tanhf(q2.y*inv)); q2.z=rt(tanhf(q2.z*inv)); q2.w=rt(tanhf(q2.w*inv));
        q3.x=rt(tanhf(q3.x*inv)); q3.y=rt(tanhf(q3.y*inv)); q3.z=rt(tanhf(q3.z*inv)); q3.w=rt(tanhf(q3.w*inv));
        *(float4*)&sm[ZZ + row*68 + sg*16]      = q0;
        *(float4*)&sm[ZZ + row*68 + sg*16 + 4]  = q1;
        *(float4*)&sm[ZZ + row*68 + sg*16 + 8]  = q2;
        *(float4*)&sm[ZZ + row*68 + sg*16 + 12] = q3;
        #pragma unroll 4
        for (int i = 0; i < 8; i++) {
            int q = tid + i*256, r = q >> 5, c4 = q & 31;
            float4* p = (float4*)&sm[XMF + r*260 + c4*4];
            float4 v = *p;
            v.x=rt(tanhf(v.x)); v.y=rt(tanhf(v.y)); v.z=rt(tanhf(v.z)); v.w=rt(tanhf(v.w));
            *p = v;
        }
    }
    __syncthreads();

    // ---------------- P3: fc2 [64x64], K=192 = [z | tanh(m)] ----------------
    {
        const int rb = (wid >> 1) * 16, nb = (wid & 1) * 32;
        float ac[4][4] = {};
        mt<8,4,68,196>(ac, sm + ZZ + rb*68, sm + F2W + nb*196);
        mt<16,4,260,196>(ac, sm + XMF + rb*260 + 128, sm + F2W + nb*196 + 64);
        #pragma unroll
        for (int n = 0; n < 4; n++) {
            int cb = nb + n*8 + 2*l4, r = rb + g;
            sm[Z2 + r*68 + cb]       = rt(tanhf(ac[n][0] + sm[PF2B+cb]));
            sm[Z2 + r*68 + cb+1]     = rt(tanhf(ac[n][1] + sm[PF2B+cb+1]));
            sm[Z2 + (r+8)*68 + cb]   = rt(tanhf(ac[n][2] + sm[PF2B+cb]));
            sm[Z2 + (r+8)*68 + cb+1] = rt(tanhf(ac[n][3] + sm[PF2B+cb+1]));
        }
    }
    __syncthreads();

    // ---------------- P4: fc3 (warps 0-3) || prefetch W1 q0 (warps 4-7) ----------------
    if (wid < 4) {
        const int rb = wid * 16;
        float ac[4][4] = {};
        mt<8,4,68,68>(ac, sm + Z2 + rb*68, sm + F3W);
        #pragma unroll
        for (int n = 0; n < 4; n++) {
            int cb = n*8 + 2*l4, r = rb + g;
            sm[MSGR + r*36 + cb]       = ac[n][0] + sm[PF3B+cb];
            sm[MSGR + r*36 + cb+1]     = ac[n][1] + sm[PF3B+cb+1];
            sm[MSGR + (r+8)*36 + cb]   = ac[n][2] + sm[PF3B+cb];
            sm[MSGR + (r+8)*36 + cb+1] = ac[n][3] + sm[PF3B+cb+1];
        }
    } else {
        ldq(sbu + BUF2(wid,0)*4, wsl1, lane);
    }
    __syncthreads();

    // ---------------- P5: msg l2norm -> out (warps 4-7) || prefetch W1 q0 (warps 0-3) ----------------
    if (tid >= 128) {
        int t = tid - 128, row = t >> 1, sg = t & 1;
        float4 q0 = *(float4*)&sm[MSGR + row*36 + sg*16];
        float4 q1 = *(float4*)&sm[MSGR + row*36 + sg*16 + 4];
        float4 q2 = *(float4*)&sm[MSGR + row*36 + sg*16 + 8];
        float4 q3 = *(float4*)&sm[MSGR + row*36 + sg*16 + 12];
        float ss = q0.x*q0.x+q0.y*q0.y+q0.z*q0.z+q0.w*q0.w
                 + q1.x*q1.x+q1.y*q1.y+q1.z*q1.z+q1.w*q1.w
                 + q2.x*q2.x+q2.y*q2.y+q2.z*q2.z+q2.w*q2.w
                 + q3.x*q3.x+q3.y*q3.y+q3.z*q3.z+q3.w*q3.w;
        ss += __shfl_xor_sync(~0u, ss, 1);
        float inv = 1.0f / fmaxf(sqrtf(ss), 1e-12f);
        float4* og = (float4*)(out + (r0 + row)*32 + sg*16);
        og[0] = make_float4(q0.x*inv, q0.y*inv, q0.z*inv, q0.w*inv);
        og[1] = make_float4(q1.x*inv, q1.y*inv, q1.z*inv, q1.w*inv);
        og[2] = make_float4(q2.x*inv, q2.y*inv, q2.z*inv, q2.w*inv);
        og[3] = make_float4(q3.x*inv, q3.y*inv, q3.z*inv, q3.w*inv);
    } else {
        ldq(sbu + BUF2(wid,0)*4, wsl1, lane);
    }
    __syncthreads();

    // ---------------- action L1: all 8 warps, per-warp cp.async pipeline ----------------
    const int nb = wid * 32;
    float h1a[4][4][4];
    #pragma unroll
    for (int s = 0; s < 4; s++)
        #pragma unroll
        for (int t = 0; t < 4; t++)
            h1a[s][t][0]=h1a[s][t][1]=h1a[s][t][2]=h1a[s][t][3]=0.f;
    #pragma unroll
    for (int q = 0; q < 4; q++) {
        if (q < 3) ldq(sbu + BUF2(wid,(q+1)&1)*4, wsl1 + (q+1)*64, lane);
        else       ldq(sbu + BUF2(wid,0)*4,       wsl2,            lane);
        CPWAIT1();
        mma64k<8>(h1a, sm + XMF + q*64, sm + BUF2(wid, q&1));
    }
    __syncthreads();
    // h1 writeback: relu + bias + tf32, each warp its own n32 columns
    #pragma unroll
    for (int s = 0; s < 4; s++)
        #pragma unroll
        for (int t = 0; t < 4; t++) {
            int cb = nb + t*8 + 2*l4, r = s*16 + g;
            float ba = sm[PB1+cb], bb = sm[PB1+cb+1];
            *(float2*)&sm[XMF + r*260 + cb] =
                make_float2(rt(fmaxf(h1a[s][t][0]+ba,0.f)), rt(fmaxf(h1a[s][t][1]+bb,0.f)));
            *(float2*)&sm[XMF + (r+8)*260 + cb] =
                make_float2(rt(fmaxf(h1a[s][t][2]+ba,0.f)), rt(fmaxf(h1a[s][t][3]+bb,0.f)));
        }
    __syncthreads();

    // ---------------- action L2: fused w3 dot, h2 never stored ----------------
    float ac[4][4][4];
    #pragma unroll
    for (int s = 0; s < 4; s++)
        #pragma unroll
        for (int t = 0; t < 4; t++)
            ac[s][t][0]=ac[s][t][1]=ac[s][t][2]=ac[s][t][3]=0.f;
    #pragma unroll
    for (int q = 0; q < 4; q++) {
        if (q < 3) { ldq(sbu + BUF2(wid,(q+1)&1)*4, wsl2 + (q+1)*64, lane); CPWAIT1(); }
        else       { CPWAIT0(); }
        mma64k<8>(ac, sm + XMF + q*64, sm + BUF2(wid, q&1));
    }
    float pr[8] = {0,0,0,0,0,0,0,0};
    #pragma unroll
    for (int s = 0; s < 4; s++)
        #pragma unroll
        for (int t = 0; t < 4; t++) {
            int cb = nb + t*8 + 2*l4;
            float ba = sm[PB2+cb], bb = sm[PB2+cb+1];
            float wa = sm[PW3+cb], wb = sm[PW3+cb+1];
            pr[2*s]   += fmaxf(ac[s][t][0]+ba,0.f)*wa + fmaxf(ac[s][t][1]+bb,0.f)*wb;
            pr[2*s+1] += fmaxf(ac[s][t][2]+ba,0.f)*wa + fmaxf(ac[s][t][3]+bb,0.f)*wb;
        }
    #pragma unroll
    for (int i = 0; i < 8; i++) {
        pr[i] += __shfl_xor_sync(~0u, pr[i], 1);
        pr[i] += __shfl_xor_sync(~0u, pr[i], 2);
    }
    if (l4 == 0) {
        #pragma unroll
        for (int s = 0; s < 4; s++) {
            atomicAdd(&sm[SMACT + s*16 + g],     pr[2*s]);
            atomicAdd(&sm[SMACT + s*16 + 8 + g], pr[2*s+1]);
        }
    }
    __syncthreads();
    if (tid < 64)
        out[(long)Bn*32 + r0 + tid] = tanhf(sm[SMACT+tid] + sm[PB3]);
}

extern "C" void kernel_launch(void* const* d_in, const int* in_sizes, int n_in,
                              void* d_out, int out_size) {
    const float* x   = (const float*)d_in[0];
    const float* m   = (const float*)d_in[1];
    const float* f1w = (const float*)d_in[2];
    const float* f1b = (const float*)d_in[3];
    const float* f2w = (const float*)d_in[4];
    const float* f2b = (const float*)d_in[5];
    const float* f3w = (const float*)d_in[6];
    const float* f3b = (const float*)d_in[7];
    const float* w1  = (const float*)d_in[8];
    const float* b1  = (const float*)d_in[9];
    const float* w2  = (const float*)d_in[10];
    const float* b2  = (const float*)d_in[11];
    const float* w3  = (const float*)d_in[12];
    const float* b3  = (const float*)d_in[13];
    float* out = (float*)d_out;

    int Bn = in_sizes[0] / 128;
    prep_weights<<<128, 256>>>(f1w, f2w, f3w, w1, w2);
    cudaFuncSetAttribute(actor_kernel, cudaFuncAttributeMaxDynamicSharedMemorySize, SMEMB);
    actor_kernel<<<Bn / 64, 256, SMEMB>>>(x, m, f1b, f2b, f3b,
                                          b1, b2, w3, b3, out, Bn);
}